// round 2
// baseline (speedup 1.0000x reference)
#include <cuda_runtime.h>
#include <math.h>

// Problem constants (fixed by the reference: B=8, H=W=128, DIM=128, HEADS=4, HD=32, MLP=512, DEPTH=4)
#define MTOT 131072          // 8 * 16384 tokens
#define SPATIAL 128

// Scratch (static device globals: allocation-free, graph-capture safe)
__device__ float g_qkv[(size_t)MTOT * 384];   // [token][q(128) | k(128) | v(128)], inner = head*32 + c
__device__ float g_o  [(size_t)MTOT * 128];   // attention output, merged heads
__device__ float g_h  [(size_t)MTOT * 512];   // MLP hidden

__device__ __forceinline__ float gelu_exact(float a) {
    return 0.5f * a * (1.0f + erff(a * 0.70710678118654752440f));
}

// ---------------------------------------------------------------------------
// Kernel 1: y = LN1(x); qkv = y @ Wqkv   (M=131072, K=128, N=384)
// CTA: 64 tokens, 256 threads. A (LN output) staged k-major in smem; N in 6 chunks of 64.
// ---------------------------------------------------------------------------
__global__ __launch_bounds__(256) void k_ln1_qkv(
    const float* __restrict__ X, const float* __restrict__ gamma,
    const float* __restrict__ beta, const float* __restrict__ W)
{
    extern __shared__ float sm[];
    float (*A)[64]  = (float (*)[64])sm;            // [128][64] k-major
    float (*Bs)[64] = (float (*)[64])(sm + 8192);   // [128][64]
    const int tid = threadIdx.x;
    const int m0  = blockIdx.x * 64;

    // ---- LayerNorm of 64 tokens, transposed into A ----
    {
        const int t  = tid >> 2;
        const int cs = (tid & 3) * 32;
        const float4* xr = (const float4*)(X + (size_t)(m0 + t) * 128 + cs);
        float v[32]; float s = 0.f, sq = 0.f;
#pragma unroll
        for (int i = 0; i < 8; i++) {
            float4 f = xr[i];
            v[4*i+0]=f.x; v[4*i+1]=f.y; v[4*i+2]=f.z; v[4*i+3]=f.w;
            s  += f.x + f.y + f.z + f.w;
            sq += f.x*f.x + f.y*f.y + f.z*f.z + f.w*f.w;
        }
        s  += __shfl_xor_sync(0xffffffffu, s , 1);
        sq += __shfl_xor_sync(0xffffffffu, sq, 1);
        s  += __shfl_xor_sync(0xffffffffu, s , 2);
        sq += __shfl_xor_sync(0xffffffffu, sq, 2);
        const float mean = s * (1.f/128.f);
        const float rstd = rsqrtf(sq*(1.f/128.f) - mean*mean + 1e-3f);
#pragma unroll
        for (int i = 0; i < 32; i++) {
            const int k = cs + i;
            A[k][t] = (v[i] - mean) * rstd * gamma[k] + beta[k];
        }
    }

    const int ty = tid >> 4, tx = tid & 15;
    float* outp = g_qkv + (size_t)m0 * 384;
    for (int nc = 0; nc < 6; nc++) {
        __syncthreads();
#pragma unroll
        for (int i = 0; i < 8; i++) {
            const int idx = tid + i * 256;
            const int k = idx >> 4, n4 = idx & 15;
            ((float4*)Bs[k])[n4] = ((const float4*)(W + k*384 + nc*64))[n4];
        }
        __syncthreads();
        float acc[4][4] = {};
#pragma unroll 8
        for (int k = 0; k < 128; k++) {
            const float4 a = *(const float4*)&A[k][ty*4];
            const float4 b = *(const float4*)&Bs[k][tx*4];
            acc[0][0]+=a.x*b.x; acc[0][1]+=a.x*b.y; acc[0][2]+=a.x*b.z; acc[0][3]+=a.x*b.w;
            acc[1][0]+=a.y*b.x; acc[1][1]+=a.y*b.y; acc[1][2]+=a.y*b.z; acc[1][3]+=a.y*b.w;
            acc[2][0]+=a.z*b.x; acc[2][1]+=a.z*b.y; acc[2][2]+=a.z*b.z; acc[2][3]+=a.z*b.w;
            acc[3][0]+=a.w*b.x; acc[3][1]+=a.w*b.y; acc[3][2]+=a.w*b.z; acc[3][3]+=a.w*b.w;
        }
#pragma unroll
        for (int i = 0; i < 4; i++) {
            *(float4*)(outp + (size_t)(ty*4+i)*384 + nc*64 + tx*4) =
                make_float4(acc[i][0], acc[i][1], acc[i][2], acc[i][3]);
        }
    }
}

// ---------------------------------------------------------------------------
// Kernel 2: local 3x3 attention. CTA = 16x16 spatial tile of one image,
// loops 4 heads; K/V halo (18x18, zero-padded like the reference) in smem.
// One thread per token. Padded stride 36 avoids smem bank conflicts.
// ---------------------------------------------------------------------------
__global__ __launch_bounds__(256) void k_attn()
{
    extern __shared__ float sm[];
    float* ksh = sm;              // 18*18*36 = 11664 floats
    float* vsh = sm + 11664;
    float* qo  = sm + 2*11664;    // 256*36 = 9216 floats
    const int tid = threadIdx.x;
    const int b   = blockIdx.z;
    const int ti0 = blockIdx.y * 16, tj0 = blockIdx.x * 16;
    const size_t img_base = (size_t)b * (SPATIAL * SPATIAL);

    for (int head = 0; head < 4; head++) {
        if (head) __syncthreads();
        const int qoff = head*32, koff = 128 + head*32, voff = 256 + head*32;

        // halo K/V (zeros outside the image, matching reference zero-pad)
        for (int idx = tid; idx < 18*18*32; idx += 256) {
            const int c  = idx & 31;
            const int rc = idx >> 5;
            const int r  = rc / 18, cl = rc % 18;
            const int gi = ti0 + r - 1, gj = tj0 + cl - 1;
            float kv = 0.f, vv = 0.f;
            if (gi >= 0 && gi < SPATIAL && gj >= 0 && gj < SPATIAL) {
                const float* p = g_qkv + (img_base + (size_t)gi*SPATIAL + gj) * 384;
                kv = p[koff + c]; vv = p[voff + c];
            }
            ksh[rc*36 + c] = kv;
            vsh[rc*36 + c] = vv;
        }
        // q tile (coalesced)
        for (int idx = tid; idx < 256*32; idx += 256) {
            const int c = idx & 31, t = idx >> 5;
            const int gi = ti0 + (t >> 4), gj = tj0 + (t & 15);
            qo[t*36 + c] = g_qkv[(img_base + (size_t)gi*SPATIAL + gj)*384 + qoff + c];
        }
        __syncthreads();

        const int t = tid, lti = t >> 4, ltj = t & 15;
        float q[32];
#pragma unroll
        for (int i = 0; i < 8; i++) {
            float4 f = *(const float4*)&qo[t*36 + i*4];
            q[4*i+0]=f.x; q[4*i+1]=f.y; q[4*i+2]=f.z; q[4*i+3]=f.w;
        }
        float lg[9];
#pragma unroll
        for (int nb = 0; nb < 9; nb++) {
            const float* kp = &ksh[((lti + nb/3)*18 + (ltj + nb%3))*36];
            float d = 0.f;
#pragma unroll
            for (int i = 0; i < 8; i++) {
                float4 f = *(const float4*)&kp[i*4];
                d += q[4*i]*f.x + q[4*i+1]*f.y + q[4*i+2]*f.z + q[4*i+3]*f.w;
            }
            lg[nb] = d * 0.17677669529663687f;   // 32^-0.5
        }
        float mx = lg[0];
#pragma unroll
        for (int nb = 1; nb < 9; nb++) mx = fmaxf(mx, lg[nb]);
        float p[9], Z = 0.f;
#pragma unroll
        for (int nb = 0; nb < 9; nb++) { p[nb] = expf(lg[nb] - mx); Z += p[nb]; }
        const float inv = 1.f / Z;
        float o[32] = {};
#pragma unroll
        for (int nb = 0; nb < 9; nb++) {
            const float wgt = p[nb] * inv;
            const float* vp = &vsh[((lti + nb/3)*18 + (ltj + nb%3))*36];
#pragma unroll
            for (int i = 0; i < 8; i++) {
                float4 f = *(const float4*)&vp[i*4];
                o[4*i+0] += wgt*f.x; o[4*i+1] += wgt*f.y;
                o[4*i+2] += wgt*f.z; o[4*i+3] += wgt*f.w;
            }
        }
        // stage own row (no cross-thread hazard: each thread reads/writes only row t)
#pragma unroll
        for (int i = 0; i < 8; i++)
            *(float4*)&qo[t*36 + i*4] = make_float4(o[4*i], o[4*i+1], o[4*i+2], o[4*i+3]);
        __syncthreads();
        // coalesced writeout
        for (int idx = tid; idx < 256*32; idx += 256) {
            const int c = idx & 31, tt = idx >> 5;
            const int gi = ti0 + (tt >> 4), gj = tj0 + (tt & 15);
            g_o[(img_base + (size_t)gi*SPATIAL + gj)*128 + head*32 + c] = qo[tt*36 + c];
        }
    }
}

// ---------------------------------------------------------------------------
// Kernel 3: x += o @ out_w + out_b   (K=128, N=128 in 2 chunks)
// ---------------------------------------------------------------------------
__global__ __launch_bounds__(256) void k_proj_res(
    const float* __restrict__ W, const float* __restrict__ bias, float* __restrict__ X)
{
    extern __shared__ float sm[];
    float (*A)[64]  = (float (*)[64])sm;
    float (*Bs)[64] = (float (*)[64])(sm + 8192);
    const int tid = threadIdx.x;
    const int m0  = blockIdx.x * 64;
    {
        const int t = tid >> 2, cs = (tid & 3) * 32;
        const float4* orow = (const float4*)(g_o + (size_t)(m0 + t)*128 + cs);
#pragma unroll
        for (int i = 0; i < 8; i++) {
            float4 f = orow[i];
            A[cs+4*i+0][t]=f.x; A[cs+4*i+1][t]=f.y; A[cs+4*i+2][t]=f.z; A[cs+4*i+3][t]=f.w;
        }
    }
    const int ty = tid >> 4, tx = tid & 15;
    for (int nc = 0; nc < 2; nc++) {
        __syncthreads();
#pragma unroll
        for (int i = 0; i < 8; i++) {
            const int idx = tid + i*256;
            const int k = idx >> 4, n4 = idx & 15;
            ((float4*)Bs[k])[n4] = ((const float4*)(W + k*128 + nc*64))[n4];
        }
        __syncthreads();
        float acc[4][4] = {};
#pragma unroll 8
        for (int k = 0; k < 128; k++) {
            const float4 a = *(const float4*)&A[k][ty*4];
            const float4 b = *(const float4*)&Bs[k][tx*4];
            acc[0][0]+=a.x*b.x; acc[0][1]+=a.x*b.y; acc[0][2]+=a.x*b.z; acc[0][3]+=a.x*b.w;
            acc[1][0]+=a.y*b.x; acc[1][1]+=a.y*b.y; acc[1][2]+=a.y*b.z; acc[1][3]+=a.y*b.w;
            acc[2][0]+=a.z*b.x; acc[2][1]+=a.z*b.y; acc[2][2]+=a.z*b.z; acc[2][3]+=a.z*b.w;
            acc[3][0]+=a.w*b.x; acc[3][1]+=a.w*b.y; acc[3][2]+=a.w*b.z; acc[3][3]+=a.w*b.w;
        }
        const float4 bb = *(const float4*)(bias + nc*64 + tx*4);
#pragma unroll
        for (int i = 0; i < 4; i++) {
            float* xp = X + (size_t)(m0+ty*4+i)*128 + nc*64 + tx*4;
            float4 xo = *(float4*)xp;
            *(float4*)xp = make_float4(acc[i][0]+xo.x+bb.x, acc[i][1]+xo.y+bb.y,
                                       acc[i][2]+xo.z+bb.z, acc[i][3]+xo.w+bb.w);
        }
    }
}

// ---------------------------------------------------------------------------
// Kernel 4: y = LN2(x); h = gelu(y @ W1 + b1)   (K=128, N=512 in 8 chunks)
// ---------------------------------------------------------------------------
__global__ __launch_bounds__(256) void k_ln2_ff1(
    const float* __restrict__ X, const float* __restrict__ gamma,
    const float* __restrict__ beta, const float* __restrict__ W,
    const float* __restrict__ bias)
{
    extern __shared__ float sm[];
    float (*A)[64]  = (float (*)[64])sm;
    float (*Bs)[64] = (float (*)[64])(sm + 8192);
    const int tid = threadIdx.x;
    const int m0  = blockIdx.x * 64;
    {
        const int t = tid >> 2, cs = (tid & 3) * 32;
        const float4* xr = (const float4*)(X + (size_t)(m0 + t)*128 + cs);
        float v[32]; float s = 0.f, sq = 0.f;
#pragma unroll
        for (int i = 0; i < 8; i++) {
            float4 f = xr[i];
            v[4*i+0]=f.x; v[4*i+1]=f.y; v[4*i+2]=f.z; v[4*i+3]=f.w;
            s  += f.x + f.y + f.z + f.w;
            sq += f.x*f.x + f.y*f.y + f.z*f.z + f.w*f.w;
        }
        s  += __shfl_xor_sync(0xffffffffu, s , 1);
        sq += __shfl_xor_sync(0xffffffffu, sq, 1);
        s  += __shfl_xor_sync(0xffffffffu, s , 2);
        sq += __shfl_xor_sync(0xffffffffu, sq, 2);
        const float mean = s * (1.f/128.f);
        const float rstd = rsqrtf(sq*(1.f/128.f) - mean*mean + 1e-3f);
#pragma unroll
        for (int i = 0; i < 32; i++) {
            const int k = cs + i;
            A[k][t] = (v[i] - mean) * rstd * gamma[k] + beta[k];
        }
    }
    const int ty = tid >> 4, tx = tid & 15;
    float* outp = g_h + (size_t)m0 * 512;
    for (int nc = 0; nc < 8; nc++) {
        __syncthreads();
#pragma unroll
        for (int i = 0; i < 8; i++) {
            const int idx = tid + i*256;
            const int k = idx >> 4, n4 = idx & 15;
            ((float4*)Bs[k])[n4] = ((const float4*)(W + k*512 + nc*64))[n4];
        }
        __syncthreads();
        float acc[4][4] = {};
#pragma unroll 8
        for (int k = 0; k < 128; k++) {
            const float4 a = *(const float4*)&A[k][ty*4];
            const float4 b = *(const float4*)&Bs[k][tx*4];
            acc[0][0]+=a.x*b.x; acc[0][1]+=a.x*b.y; acc[0][2]+=a.x*b.z; acc[0][3]+=a.x*b.w;
            acc[1][0]+=a.y*b.x; acc[1][1]+=a.y*b.y; acc[1][2]+=a.y*b.z; acc[1][3]+=a.y*b.w;
            acc[2][0]+=a.z*b.x; acc[2][1]+=a.z*b.y; acc[2][2]+=a.z*b.z; acc[2][3]+=a.z*b.w;
            acc[3][0]+=a.w*b.x; acc[3][1]+=a.w*b.y; acc[3][2]+=a.w*b.z; acc[3][3]+=a.w*b.w;
        }
        const float4 bb = *(const float4*)(bias + nc*64 + tx*4);
#pragma unroll
        for (int i = 0; i < 4; i++) {
            *(float4*)(outp + (size_t)(ty*4+i)*512 + nc*64 + tx*4) =
                make_float4(gelu_exact(acc[i][0]+bb.x), gelu_exact(acc[i][1]+bb.y),
                            gelu_exact(acc[i][2]+bb.z), gelu_exact(acc[i][3]+bb.w));
        }
    }
}

// ---------------------------------------------------------------------------
// Kernel 5: x += h @ W2 + b2   (K=512 tiled by 128, N=128 in one pass)
// ---------------------------------------------------------------------------
#define FMA4P(p, av, bv) { (p)[0]+=(av)*(bv).x; (p)[1]+=(av)*(bv).y; (p)[2]+=(av)*(bv).z; (p)[3]+=(av)*(bv).w; }

__global__ __launch_bounds__(256) void k_ff2_res(
    const float* __restrict__ W, const float* __restrict__ bias, float* __restrict__ X)
{
    extern __shared__ float sm[];
    float (*A)[64]   = (float (*)[64])sm;            // [128][64]
    float (*Bs)[128] = (float (*)[128])(sm + 8192);  // [128][128]
    const int tid = threadIdx.x;
    const int m0  = blockIdx.x * 64;
    const int t = tid >> 2, cs = (tid & 3) * 32;
    const int ty = tid >> 4, tx = tid & 15;
    float acc[4][8] = {};

    for (int kt = 0; kt < 4; kt++) {
        if (kt) __syncthreads();
        const float4* hr = (const float4*)(g_h + (size_t)(m0 + t)*512 + kt*128 + cs);
#pragma unroll
        for (int i = 0; i < 8; i++) {
            float4 f = hr[i];
            A[cs+4*i+0][t]=f.x; A[cs+4*i+1][t]=f.y; A[cs+4*i+2][t]=f.z; A[cs+4*i+3][t]=f.w;
        }
#pragma unroll
        for (int i = 0; i < 16; i++) {
            const int idx = tid + i*256;
            const int k = idx >> 5, n4 = idx & 31;
            ((float4*)Bs[k])[n4] = ((const float4*)(W + (size_t)(kt*128 + k)*128))[n4];
        }
        __syncthreads();
#pragma unroll 4
        for (int k = 0; k < 128; k++) {
            const float4 a  = *(const float4*)&A[k][ty*4];
            const float4 b0 = *(const float4*)&Bs[k][tx*4];
            const float4 b1 = *(const float4*)&Bs[k][tx*4 + 64];
            FMA4P(acc[0],   a.x, b0); FMA4P(acc[0]+4, a.x, b1);
            FMA4P(acc[1],   a.y, b0); FMA4P(acc[1]+4, a.y, b1);
            FMA4P(acc[2],   a.z, b0); FMA4P(acc[2]+4, a.z, b1);
            FMA4P(acc[3],   a.w, b0); FMA4P(acc[3]+4, a.w, b1);
        }
    }
    const float4 bb0 = *(const float4*)(bias + tx*4);
    const float4 bb1 = *(const float4*)(bias + 64 + tx*4);
#pragma unroll
    for (int i = 0; i < 4; i++) {
        float* xrow = X + (size_t)(m0 + ty*4 + i)*128;
        float4 x0 = *(float4*)(xrow + tx*4);
        float4 x1 = *(float4*)(xrow + 64 + tx*4);
        *(float4*)(xrow + tx*4) = make_float4(acc[i][0]+x0.x+bb0.x, acc[i][1]+x0.y+bb0.y,
                                              acc[i][2]+x0.z+bb0.z, acc[i][3]+x0.w+bb0.w);
        *(float4*)(xrow + 64 + tx*4) = make_float4(acc[i][4]+x1.x+bb1.x, acc[i][5]+x1.y+bb1.y,
                                                   acc[i][6]+x1.z+bb1.z, acc[i][7]+x1.w+bb1.w);
    }
}

// ---------------------------------------------------------------------------
// Host launcher
// ---------------------------------------------------------------------------
extern "C" void kernel_launch(void* const* d_in, const int* in_sizes, int n_in,
                              void* d_out, int out_size)
{
    (void)in_sizes; (void)n_in; (void)out_size;
    const float* x_in  = (const float*)d_in[0];
    const float* ln1_g = (const float*)d_in[1];
    const float* ln1_b = (const float*)d_in[2];
    const float* qkv_w = (const float*)d_in[3];
    const float* out_w = (const float*)d_in[4];
    const float* out_b = (const float*)d_in[5];
    const float* ln2_g = (const float*)d_in[6];
    const float* ln2_b = (const float*)d_in[7];
    const float* ff_w1 = (const float*)d_in[8];
    const float* ff_b1 = (const float*)d_in[9];
    const float* ff_w2 = (const float*)d_in[10];
    const float* ff_b2 = (const float*)d_in[11];
    float* X = (float*)d_out;

    const int SM_GEMM = 65536;                      // 2 * 128*64 floats
    const int SM_FF2  = (8192 + 16384) * 4;         // 98304
    const int SM_ATTN = (2*11664 + 9216) * 4;       // 130176
    cudaFuncSetAttribute(k_ln1_qkv, cudaFuncAttributeMaxDynamicSharedMemorySize, SM_GEMM);
    cudaFuncSetAttribute(k_proj_res, cudaFuncAttributeMaxDynamicSharedMemorySize, SM_GEMM);
    cudaFuncSetAttribute(k_ln2_ff1, cudaFuncAttributeMaxDynamicSharedMemorySize, SM_GEMM);
    cudaFuncSetAttribute(k_ff2_res, cudaFuncAttributeMaxDynamicSharedMemorySize, SM_FF2);
    cudaFuncSetAttribute(k_attn,    cudaFuncAttributeMaxDynamicSharedMemorySize, SM_ATTN);

    cudaMemcpyAsync(X, x_in, (size_t)MTOT * 128 * sizeof(float),
                    cudaMemcpyDeviceToDevice, 0);

    const int GEMM_BLOCKS = MTOT / 64;   // 2048
    dim3 gAttn(8, 8, 8);                 // (tj, ti, batch) 16x16 tiles
    for (int d = 0; d < 4; d++) {
        k_ln1_qkv<<<GEMM_BLOCKS, 256, SM_GEMM>>>(X, ln1_g + d*128, ln1_b + d*128,
                                                 qkv_w + (size_t)d*128*384);
        k_attn<<<gAttn, 256, SM_ATTN>>>();
        k_proj_res<<<GEMM_BLOCKS, 256, SM_GEMM>>>(out_w + (size_t)d*128*128,
                                                  out_b + d*128, X);
        k_ln2_ff1<<<GEMM_BLOCKS, 256, SM_GEMM>>>(X, ln2_g + d*128, ln2_b + d*128,
                                                 ff_w1 + (size_t)d*128*512, ff_b1 + d*512);
        k_ff2_res<<<GEMM_BLOCKS, 256, SM_FF2>>>(ff_w2 + (size_t)d*512*128,
                                                ff_b2 + d*128, X);
    }
}

// round 5
// speedup vs baseline: 2.5372x; 2.5372x over previous
#include <cuda_runtime.h>
#include <cuda_bf16.h>
#include <math.h>
#include <stdint.h>

#define MTOT 131072
#define SPATIAL 128

__device__ float g_qkv[(size_t)MTOT * 384];
__device__ float g_o  [(size_t)MTOT * 128];
__device__ float g_h  [(size_t)MTOT * 512];
__device__ __nv_bfloat16 g_wt[786432];  // 4 layers x 12 images x [128n][128k] bf16

__device__ __forceinline__ float gelu_exact(float a) {
    return 0.5f * a * (1.0f + erff(a * 0.70710678118654752440f));
}

__device__ __forceinline__ uint32_t smem_u32(const void* p) {
    uint32_t a;
    asm("{ .reg .u64 t; cvta.to.shared.u64 t, %1; cvt.u32.u64 %0, t; }" : "=r"(a) : "l"(p));
    return a;
}

#define LDSM4(r0, r1, r2, r3, addr) \
    asm volatile("ldmatrix.sync.aligned.m8n8.x4.shared.b16 {%0,%1,%2,%3}, [%4];" \
                 : "=r"(r0), "=r"(r1), "=r"(r2), "=r"(r3) : "r"(addr))

#define MMA16816(d, a, b) \
    asm volatile("mma.sync.aligned.m16n8k16.row.col.f32.bf16.bf16.f32 " \
                 "{%0,%1,%2,%3},{%4,%5,%6,%7},{%8,%9},{%0,%1,%2,%3};" \
                 : "+f"((d)[0]), "+f"((d)[1]), "+f"((d)[2]), "+f"((d)[3]) \
                 : "r"((a)[0]), "r"((a)[1]), "r"((a)[2]), "r"((a)[3]), \
                   "r"((b)[0]), "r"((b)[1]))

// ---------------------------------------------------------------------------
// Prep: transpose weights to n-major/k-contig bf16 images [128n][128k].
// Per layer (12 imgs): 0-2 qkv n-blocks, 3 proj, 4-7 ff1 n-blocks, 8-11 ff2 k-chunks.
// ---------------------------------------------------------------------------
__global__ __launch_bounds__(256) void k_prep(
    const float* __restrict__ qkv_w, const float* __restrict__ out_w,
    const float* __restrict__ ff_w1, const float* __restrict__ ff_w2)
{
    const int idx = blockIdx.x * 256 + threadIdx.x;   // 0..786431
    const int d   = idx / 196608;
    const int rem = idx % 196608;
    const int img = rem / 16384;
    const int pos = rem % 16384;
    const int n = pos >> 7, k = pos & 127;
    float val;
    if (img < 3)       val = qkv_w[(size_t)(d * 128 + k) * 384 + img * 128 + n];
    else if (img == 3) val = out_w[(size_t)(d * 128 + k) * 128 + n];
    else if (img < 8)  val = ff_w1[(size_t)(d * 128 + k) * 512 + (img - 4) * 128 + n];
    else               val = ff_w2[(size_t)(d * 512 + (img - 8) * 128 + k) * 128 + n];
    g_wt[idx] = __float2bfloat16(val);
}

// ---------------------------------------------------------------------------
// Unified warp-MMA bf16 GEMM. CTA = 128 tokens, 256 threads (8 warps, 2M x 4N).
// NB n-blocks of 128; KC k-chunks of 128. SRC: 0=X(+LN), 1=g_o, 2=g_h.
// EPI: 0 -> g_qkv store; 1 -> g_h = gelu(v+b); 2 -> Xout += v+b.
// smem: A [128][136] bf16 @0 (34816 B), B [128][136] bf16 @34816. Total 69632 B.
// Row stride 272 B = 17*16 B -> 8 consecutive rows hit distinct 16B sub-banks
// (16*l mod 128 distinct) -> conflict-free ldmatrix without swizzle.
// ---------------------------------------------------------------------------
template<int NB, int KC, int SRC, int EPI, int IMG0>
__global__ void __launch_bounds__(256) k_tg(
    const float* __restrict__ X, const float* __restrict__ gamma,
    const float* __restrict__ beta, const float* __restrict__ bias,
    float* __restrict__ Xout, int d)
{
    extern __shared__ char smem[];
    const uint32_t sbA = smem_u32(smem);
    const uint32_t sbB = sbA + 34816;
    const int tid = threadIdx.x, wid = tid >> 5, lane = tid & 31;
    const int wm = wid >> 2, wn = wid & 3;            // 2 M-warps x 4 N-warps
    const int m0 = blockIdx.x * 128;

    const __nv_bfloat16* wt = g_wt + (size_t)d * 196608 + (size_t)IMG0 * 16384;

    // per-warp ldmatrix base addresses
    const uint32_t aBase = sbA + (uint32_t)((wm * 64 + (lane & 15)) * 272 + (lane >> 4) * 16);
    const uint32_t bBase = sbB + (uint32_t)((wn * 32 + ((lane >> 4) * 8) + (lane & 7)) * 272
                                            + ((lane >> 3) & 1) * 16);

    for (int nb = 0; nb < NB; nb++) {
        float acc[4][4][4];
#pragma unroll
        for (int mt = 0; mt < 4; mt++)
#pragma unroll
            for (int nt = 0; nt < 4; nt++)
#pragma unroll
                for (int f = 0; f < 4; f++) acc[mt][nt][f] = 0.f;

        for (int kc = 0; kc < KC; kc++) {
            if (nb > 0 || kc > 0) __syncthreads();   // previous compute done before overwrite

            if ((KC == 1 && nb == 0) || KC > 1) {    // ---- stage A (LN fused for SRC==0) ----
                const int m = tid >> 1, h = tid & 1;
                const float* ap;
                if (SRC == 0)      ap = X   + (size_t)(m0 + m) * 128 + h * 64;
                else if (SRC == 1) ap = g_o + (size_t)(m0 + m) * 128 + h * 64;
                else               ap = g_h + (size_t)(m0 + m) * 512 + kc * 128 + h * 64;
                float4 v[16];
#pragma unroll
                for (int j = 0; j < 16; j++) v[j] = ((const float4*)ap)[j];
                if (SRC == 0) {
                    float s = 0.f, sq = 0.f;
#pragma unroll
                    for (int j = 0; j < 16; j++) {
                        s  += v[j].x + v[j].y + v[j].z + v[j].w;
                        sq += v[j].x*v[j].x + v[j].y*v[j].y + v[j].z*v[j].z + v[j].w*v[j].w;
                    }
                    s  += __shfl_xor_sync(0xffffffffu, s , 1);
                    sq += __shfl_xor_sync(0xffffffffu, sq, 1);
                    const float mean = s * (1.f / 128.f);
                    const float rstd = rsqrtf(sq * (1.f / 128.f) - mean * mean + 1e-3f);
#pragma unroll
                    for (int j = 0; j < 16; j++) {
                        const int k = h * 64 + j * 4;
                        const float4 gg = *(const float4*)(gamma + k);
                        const float4 bb = *(const float4*)(beta + k);
                        v[j].x = (v[j].x - mean) * rstd * gg.x + bb.x;
                        v[j].y = (v[j].y - mean) * rstd * gg.y + bb.y;
                        v[j].z = (v[j].z - mean) * rstd * gg.z + bb.z;
                        v[j].w = (v[j].w - mean) * rstd * gg.w + bb.w;
                    }
                }
                char* arow = smem + (size_t)m * 272 + h * 128;
#pragma unroll
                for (int j = 0; j < 8; j++) {
                    __nv_bfloat16 t8[8];
                    const float4 f0 = v[2*j], f1 = v[2*j+1];
                    t8[0]=__float2bfloat16(f0.x); t8[1]=__float2bfloat16(f0.y);
                    t8[2]=__float2bfloat16(f0.z); t8[3]=__float2bfloat16(f0.w);
                    t8[4]=__float2bfloat16(f1.x); t8[5]=__float2bfloat16(f1.y);
                    t8[6]=__float2bfloat16(f1.z); t8[7]=__float2bfloat16(f1.w);
                    *(uint4*)(arow + j * 16) = *(const uint4*)t8;
                }
            }
            {   // ---- stage B: dense [128][128] bf16 image -> padded smem ----
                const uint4* s4 = (const uint4*)(wt + (size_t)(nb * KC + kc) * 16384);
                char* bs = smem + 34816;
#pragma unroll
                for (int i = 0; i < 8; i++) {
                    const int u = tid + i * 256;        // 2048 uint4
                    const int row = u >> 4, c8 = u & 15;
                    *(uint4*)(bs + (size_t)row * 272 + c8 * 16) = s4[u];
                }
            }
            __syncthreads();

            // ---- compute: 8 k-steps of m16n8k16 ----
#pragma unroll
            for (int kk = 0; kk < 8; kk++) {
                uint32_t a[4][4];
#pragma unroll
                for (int mt = 0; mt < 4; mt++)
                    LDSM4(a[mt][0], a[mt][1], a[mt][2], a[mt][3],
                          aBase + (uint32_t)(mt * 16 * 272 + kk * 32));
                uint32_t b[4][2];
#pragma unroll
                for (int nt2 = 0; nt2 < 2; nt2++)
                    LDSM4(b[nt2*2][0], b[nt2*2][1], b[nt2*2+1][0], b[nt2*2+1][1],
                          bBase + (uint32_t)(nt2 * 16 * 272 + kk * 32));
#pragma unroll
                for (int mt = 0; mt < 4; mt++)
#pragma unroll
                    for (int nt = 0; nt < 4; nt++)
                        MMA16816(acc[mt][nt], a[mt], b[nt]);
            }
        }

        // ---- epilogue: fragment layout c0,c1 -> row (lane>>2); c2,c3 -> row+8 ----
#pragma unroll
        for (int mt = 0; mt < 4; mt++) {
#pragma unroll
            for (int nt = 0; nt < 4; nt++) {
                const int r = m0 + wm * 64 + mt * 16 + (lane >> 2);
                const int c = nb * 128 + wn * 32 + nt * 8 + (lane & 3) * 2;
                float2 bv = make_float2(0.f, 0.f);
                if (EPI != 0) bv = *(const float2*)(bias + c);
#pragma unroll
                for (int hrow = 0; hrow < 2; hrow++) {
                    const size_t row = (size_t)(r + hrow * 8);
                    const float u0 = acc[mt][nt][hrow*2+0], u1 = acc[mt][nt][hrow*2+1];
                    if (EPI == 0) {
                        *(float2*)(g_qkv + row * 384 + c) = make_float2(u0, u1);
                    } else if (EPI == 1) {
                        *(float2*)(g_h + row * 512 + c) =
                            make_float2(gelu_exact(u0 + bv.x), gelu_exact(u1 + bv.y));
                    } else {
                        float2 xo = *(float2*)(Xout + row * 128 + c);
                        *(float2*)(Xout + row * 128 + c) =
                            make_float2(xo.x + u0 + bv.x, xo.y + u1 + bv.y);
                    }
                }
            }
        }
    }
}

// ---------------------------------------------------------------------------
// Local 3x3 attention (unchanged from passing R1 kernel).
// ---------------------------------------------------------------------------
__global__ __launch_bounds__(256) void k_attn()
{
    extern __shared__ float sm[];
    float* ksh = sm;
    float* vsh = sm + 11664;
    float* qo  = sm + 2 * 11664;
    const int tid = threadIdx.x;
    const int b   = blockIdx.z;
    const int ti0 = blockIdx.y * 16, tj0 = blockIdx.x * 16;
    const size_t img_base = (size_t)b * (SPATIAL * SPATIAL);

    for (int head = 0; head < 4; head++) {
        if (head) __syncthreads();
        const int qoff = head * 32, koff = 128 + head * 32, voff = 256 + head * 32;
        for (int idx = tid; idx < 18 * 18 * 32; idx += 256) {
            const int c = idx & 31, rc = idx >> 5;
            const int r = rc / 18, cl = rc % 18;
            const int gi = ti0 + r - 1, gj = tj0 + cl - 1;
            float kv = 0.f, vv = 0.f;
            if (gi >= 0 && gi < SPATIAL && gj >= 0 && gj < SPATIAL) {
                const float* p = g_qkv + (img_base + (size_t)gi * SPATIAL + gj) * 384;
                kv = p[koff + c]; vv = p[voff + c];
            }
            ksh[rc * 36 + c] = kv;
            vsh[rc * 36 + c] = vv;
        }
        for (int idx = tid; idx < 256 * 32; idx += 256) {
            const int c = idx & 31, t = idx >> 5;
            const int gi = ti0 + (t >> 4), gj = tj0 + (t & 15);
            qo[t * 36 + c] = g_qkv[(img_base + (size_t)gi * SPATIAL + gj) * 384 + qoff + c];
        }
        __syncthreads();

        const int t = tid, lti = t >> 4, ltj = t & 15;
        float q[32];
#pragma unroll
        for (int i = 0; i < 8; i++) {
            float4 f = *(const float4*)&qo[t * 36 + i * 4];
            q[4*i+0]=f.x; q[4*i+1]=f.y; q[4*i+2]=f.z; q[4*i+3]=f.w;
        }
        float lg[9];
#pragma unroll
        for (int nb = 0; nb < 9; nb++) {
            const float* kp = &ksh[((lti + nb/3)*18 + (ltj + nb%3))*36];
            float dd = 0.f;
#pragma unroll
            for (int i = 0; i < 8; i++) {
                float4 f = *(const float4*)&kp[i*4];
                dd += q[4*i]*f.x + q[4*i+1]*f.y + q[4*i+2]*f.z + q[4*i+3]*f.w;
            }
            lg[nb] = dd * 0.17677669529663687f;
        }
        float mx = lg[0];
#pragma unroll
        for (int nb = 1; nb < 9; nb++) mx = fmaxf(mx, lg[nb]);
        float p9[9], Z = 0.f;
#pragma unroll
        for (int nb = 0; nb < 9; nb++) { p9[nb] = expf(lg[nb] - mx); Z += p9[nb]; }
        const float inv = 1.f / Z;
        float o[32] = {};
#pragma unroll
        for (int nb = 0; nb < 9; nb++) {
            const float wgt = p9[nb] * inv;
            const float* vp = &vsh[((lti + nb/3)*18 + (ltj + nb%3))*36];
#pragma unroll
            for (int i = 0; i < 8; i++) {
                float4 f = *(const float4*)&vp[i*4];
                o[4*i+0]+=wgt*f.x; o[4*i+1]+=wgt*f.y; o[4*i+2]+=wgt*f.z; o[4*i+3]+=wgt*f.w;
            }
        }
#pragma unroll
        for (int i = 0; i < 8; i++)
            *(float4*)&qo[t*36 + i*4] = make_float4(o[4*i], o[4*i+1], o[4*i+2], o[4*i+3]);
        __syncthreads();
        for (int idx = tid; idx < 256 * 32; idx += 256) {
            const int c = idx & 31, tt = idx >> 5;
            const int gi = ti0 + (tt >> 4), gj = tj0 + (tt & 15);
            g_o[(img_base + (size_t)gi * SPATIAL + gj) * 128 + head * 32 + c] = qo[tt * 36 + c];
        }
    }
}

// ---------------------------------------------------------------------------
extern "C" void kernel_launch(void* const* d_in, const int* in_sizes, int n_in,
                              void* d_out, int out_size)
{
    (void)in_sizes; (void)n_in; (void)out_size;
    const float* x_in  = (const float*)d_in[0];
    const float* ln1_g = (const float*)d_in[1];
    const float* ln1_b = (const float*)d_in[2];
    const float* qkv_w = (const float*)d_in[3];
    const float* out_w = (const float*)d_in[4];
    const float* out_b = (const float*)d_in[5];
    const float* ln2_g = (const float*)d_in[6];
    const float* ln2_b = (const float*)d_in[7];
    const float* ff_w1 = (const float*)d_in[8];
    const float* ff_b1 = (const float*)d_in[9];
    const float* ff_w2 = (const float*)d_in[10];
    const float* ff_b2 = (const float*)d_in[11];
    float* X = (float*)d_out;

    const int SM_TG   = 69632;
    const int SM_ATTN = (2 * 11664 + 9216) * 4;
    cudaFuncSetAttribute(k_tg<3,1,0,0,0>, cudaFuncAttributeMaxDynamicSharedMemorySize, SM_TG);
    cudaFuncSetAttribute(k_tg<1,1,1,2,3>, cudaFuncAttributeMaxDynamicSharedMemorySize, SM_TG);
    cudaFuncSetAttribute(k_tg<4,1,0,1,4>, cudaFuncAttributeMaxDynamicSharedMemorySize, SM_TG);
    cudaFuncSetAttribute(k_tg<1,4,2,2,8>, cudaFuncAttributeMaxDynamicSharedMemorySize, SM_TG);
    cudaFuncSetAttribute(k_attn, cudaFuncAttributeMaxDynamicSharedMemorySize, SM_ATTN);

    cudaMemcpyAsync(X, x_in, (size_t)MTOT * 128 * sizeof(float),
                    cudaMemcpyDeviceToDevice, 0);
    k_prep<<<3072, 256>>>(qkv_w, out_w, ff_w1, ff_w2);

    const int GB = MTOT / 128;   // 1024 CTAs
    dim3 gAttn(8, 8, 8);
    for (int d = 0; d < 4; d++) {
        k_tg<3,1,0,0,0><<<GB, 256, SM_TG>>>(X, ln1_g + d*128, ln1_b + d*128, out_b, X, d);
        k_attn<<<gAttn, 256, SM_ATTN>>>();
        k_tg<1,1,1,2,3><<<GB, 256, SM_TG>>>(X, ln1_g, ln1_b, out_b + d*128, X, d);
        k_tg<4,1,0,1,4><<<GB, 256, SM_TG>>>(X, ln2_g + d*128, ln2_b + d*128, ff_b1 + d*512, X, d);
        k_tg<1,4,2,2,8><<<GB, 256, SM_TG>>>(X, ln2_g, ln2_b, ff_b2 + d*128, X, d);
    }
}

// round 8
// speedup vs baseline: 3.2485x; 1.2804x over previous
#include <cuda_runtime.h>
#include <cuda_bf16.h>
#include <math.h>
#include <stdint.h>

#define MTOT 131072
#define SPATIAL 128

__device__ __align__(256) __nv_bfloat16 g_qkv[(size_t)MTOT * 384];
__device__ __align__(256) __nv_bfloat16 g_o  [(size_t)MTOT * 128];
__device__ __align__(256) __nv_bfloat16 g_h  [(size_t)MTOT * 512];
__device__ __align__(256) __nv_bfloat16 g_wt [786432];  // 4 layers x 12 images x [128n][128k]

__device__ __forceinline__ float gelu_exact(float a) {
    return 0.5f * a * (1.0f + erff(a * 0.70710678118654752440f));
}

__device__ __forceinline__ uint32_t smem_u32(const void* p) {
    uint32_t a;
    asm("{ .reg .u64 t; cvta.to.shared.u64 t, %1; cvt.u32.u64 %0, t; }" : "=r"(a) : "l"(p));
    return a;
}

#define LDSM4(r0, r1, r2, r3, addr) \
    asm volatile("ldmatrix.sync.aligned.m8n8.x4.shared.b16 {%0,%1,%2,%3}, [%4];" \
                 : "=r"(r0), "=r"(r1), "=r"(r2), "=r"(r3) : "r"(addr))

#define MMA16816(d, a, b) \
    asm volatile("mma.sync.aligned.m16n8k16.row.col.f32.bf16.bf16.f32 " \
                 "{%0,%1,%2,%3},{%4,%5,%6,%7},{%8,%9},{%0,%1,%2,%3};" \
                 : "+f"((d)[0]), "+f"((d)[1]), "+f"((d)[2]), "+f"((d)[3]) \
                 : "r"((a)[0]), "r"((a)[1]), "r"((a)[2]), "r"((a)[3]), \
                   "r"((b)[0]), "r"((b)[1]))

// ---------------------------------------------------------------------------
// Prep: transpose weights to n-major/k-contig bf16 images [128n][128k].
// Per layer (12 imgs): 0-2 qkv n-blocks, 3 proj, 4-7 ff1 n-blocks, 8-11 ff2 k-chunks.
// ---------------------------------------------------------------------------
__global__ __launch_bounds__(256) void k_prep(
    const float* __restrict__ qkv_w, const float* __restrict__ out_w,
    const float* __restrict__ ff_w1, const float* __restrict__ ff_w2)
{
    const int idx = blockIdx.x * 256 + threadIdx.x;   // 0..786431
    const int d   = idx / 196608;
    const int rem = idx % 196608;
    const int img = rem / 16384;
    const int pos = rem % 16384;
    const int n = pos >> 7, k = pos & 127;
    float val;
    if (img < 3)       val = qkv_w[(size_t)(d * 128 + k) * 384 + img * 128 + n];
    else if (img == 3) val = out_w[(size_t)(d * 128 + k) * 128 + n];
    else if (img < 8)  val = ff_w1[(size_t)(d * 128 + k) * 512 + (img - 4) * 128 + n];
    else               val = ff_w2[(size_t)(d * 512 + (img - 8) * 128 + k) * 128 + n];
    g_wt[idx] = __float2bfloat16(val);
}

// ---------------------------------------------------------------------------
// Unified warp-MMA bf16 GEMM. CTA = 128 tokens, 256 threads (8 warps, 2M x 4N).
// NB n-blocks of 128; KC k-chunks of 128. SRC: 0=X(+LN), 1=g_o, 2=g_h.
// EPI: 0 -> g_qkv (bf16); 1 -> g_h = gelu(v+b) (bf16); 2 -> Xout += v+b (fp32).
// smem: A [128][136] bf16 @0, B [128][136] bf16 @34816. Total 69632 B.
// Row stride 272 B -> 8 consecutive rows hit distinct 16B sub-banks (conflict-free ldsm).
// Staging via plain uint4 ld/st (same mechanics as the R5 kernel that passed).
// ---------------------------------------------------------------------------
template<int NB, int KC, int SRC, int EPI, int IMG0>
__global__ void __launch_bounds__(256) k_tg(
    const float* __restrict__ X, const float* __restrict__ gamma,
    const float* __restrict__ beta, const float* __restrict__ bias,
    float* __restrict__ Xout, int d)
{
    extern __shared__ char smem[];
    const uint32_t sbA = smem_u32(smem);
    const uint32_t sbB = sbA + 34816;
    const int tid = threadIdx.x, wid = tid >> 5, lane = tid & 31;
    const int wm = wid >> 2, wn = wid & 3;
    const int m0 = blockIdx.x * 128;

    const __nv_bfloat16* wt = g_wt + (size_t)d * 196608 + (size_t)IMG0 * 16384;

    const uint32_t aBase = sbA + (uint32_t)((wm * 64 + (lane & 15)) * 272 + (lane >> 4) * 16);
    const uint32_t bBase = sbB + (uint32_t)((wn * 32 + ((lane >> 4) * 8) + (lane & 7)) * 272
                                            + ((lane >> 3) & 1) * 16);

    for (int nb = 0; nb < NB; nb++) {
        float acc[4][4][4];
#pragma unroll
        for (int mt = 0; mt < 4; mt++)
#pragma unroll
            for (int nt = 0; nt < 4; nt++)
#pragma unroll
                for (int f = 0; f < 4; f++) acc[mt][nt][f] = 0.f;

        for (int kc = 0; kc < KC; kc++) {
            if (nb > 0 || kc > 0) __syncthreads();

            {   // ---- stage B: [128][128] bf16 image -> padded smem ----
                const uint4* s4 = (const uint4*)(wt + (size_t)(nb * KC + kc) * 16384);
                char* bs = smem + 34816;
#pragma unroll
                for (int i = 0; i < 8; i++) {
                    const int u = tid + i * 256;        // 2048 x 16B
                    const int row = u >> 4, c8 = u & 15;
                    *(uint4*)(bs + (size_t)row * 272 + c8 * 16) = s4[u];
                }
            }
            if ((KC == 1 && nb == 0) || KC > 1) {      // ---- stage A ----
                const int m = tid >> 1, h = tid & 1;
                if (SRC == 0) {                        // LN(x) fused, fp32 -> bf16
                    const float* ap = X + (size_t)(m0 + m) * 128 + h * 64;
                    float4 v[16];
#pragma unroll
                    for (int j = 0; j < 16; j++) v[j] = ((const float4*)ap)[j];
                    float s = 0.f, sq = 0.f;
#pragma unroll
                    for (int j = 0; j < 16; j++) {
                        s  += v[j].x + v[j].y + v[j].z + v[j].w;
                        sq += v[j].x*v[j].x + v[j].y*v[j].y + v[j].z*v[j].z + v[j].w*v[j].w;
                    }
                    s  += __shfl_xor_sync(0xffffffffu, s , 1);
                    sq += __shfl_xor_sync(0xffffffffu, sq, 1);
                    const float mean = s * (1.f / 128.f);
                    const float rstd = rsqrtf(sq * (1.f / 128.f) - mean * mean + 1e-3f);
                    char* arow = smem + (size_t)m * 272 + h * 128;
#pragma unroll
                    for (int j = 0; j < 8; j++) {
                        const int k = h * 64 + j * 8;
                        const float4 f0 = v[2*j], f1 = v[2*j+1];
                        const float4 g0 = *(const float4*)(gamma + k);
                        const float4 g1 = *(const float4*)(gamma + k + 4);
                        const float4 b0 = *(const float4*)(beta + k);
                        const float4 b1 = *(const float4*)(beta + k + 4);
                        __nv_bfloat16 t8[8];
                        t8[0]=__float2bfloat16((f0.x-mean)*rstd*g0.x+b0.x);
                        t8[1]=__float2bfloat16((f0.y-mean)*rstd*g0.y+b0.y);
                        t8[2]=__float2bfloat16((f0.z-mean)*rstd*g0.z+b0.z);
                        t8[3]=__float2bfloat16((f0.w-mean)*rstd*g0.w+b0.w);
                        t8[4]=__float2bfloat16((f1.x-mean)*rstd*g1.x+b1.x);
                        t8[5]=__float2bfloat16((f1.y-mean)*rstd*g1.y+b1.y);
                        t8[6]=__float2bfloat16((f1.z-mean)*rstd*g1.z+b1.z);
                        t8[7]=__float2bfloat16((f1.w-mean)*rstd*g1.w+b1.w);
                        *(uint4*)(arow + j * 16) = *(const uint4*)t8;
                    }
                } else {                               // direct bf16 copy
                    const __nv_bfloat16* ap = (SRC == 1)
                        ? g_o + (size_t)(m0 + m) * 128 + h * 64
                        : g_h + (size_t)(m0 + m) * 512 + kc * 128 + h * 64;
                    char* arow = smem + (size_t)m * 272 + h * 128;
#pragma unroll
                    for (int j = 0; j < 8; j++)
                        *(uint4*)(arow + j * 16) = ((const uint4*)ap)[j];
                }
            }
            __syncthreads();

            // ---- compute: 8 k-steps of m16n8k16 ----
#pragma unroll
            for (int kk = 0; kk < 8; kk++) {
                uint32_t a[4][4];
#pragma unroll
                for (int mt = 0; mt < 4; mt++)
                    LDSM4(a[mt][0], a[mt][1], a[mt][2], a[mt][3],
                          aBase + (uint32_t)(mt * 16 * 272 + kk * 32));
                uint32_t b[4][2];
#pragma unroll
                for (int nt2 = 0; nt2 < 2; nt2++)
                    LDSM4(b[nt2*2][0], b[nt2*2][1], b[nt2*2+1][0], b[nt2*2+1][1],
                          bBase + (uint32_t)(nt2 * 16 * 272 + kk * 32));
#pragma unroll
                for (int mt = 0; mt < 4; mt++)
#pragma unroll
                    for (int nt = 0; nt < 4; nt++)
                        MMA16816(acc[mt][nt], a[mt], b[nt]);
            }
        }

        // ---- epilogue ----
#pragma unroll
        for (int mt = 0; mt < 4; mt++) {
#pragma unroll
            for (int nt = 0; nt < 4; nt++) {
                const int r = m0 + wm * 64 + mt * 16 + (lane >> 2);
                const int c = nb * 128 + wn * 32 + nt * 8 + (lane & 3) * 2;
                float2 bv = make_float2(0.f, 0.f);
                if (EPI != 0) bv = *(const float2*)(bias + c);
#pragma unroll
                for (int hrow = 0; hrow < 2; hrow++) {
                    const size_t row = (size_t)(r + hrow * 8);
                    const float u0 = acc[mt][nt][hrow*2+0], u1 = acc[mt][nt][hrow*2+1];
                    if (EPI == 0) {
                        *(__nv_bfloat162*)(g_qkv + row * 384 + c) =
                            __floats2bfloat162_rn(u0, u1);
                    } else if (EPI == 1) {
                        *(__nv_bfloat162*)(g_h + row * 512 + c) =
                            __floats2bfloat162_rn(gelu_exact(u0 + bv.x), gelu_exact(u1 + bv.y));
                    } else {
                        float2 xo = *(float2*)(Xout + row * 128 + c);
                        *(float2*)(Xout + row * 128 + c) =
                            make_float2(xo.x + u0 + bv.x, xo.y + u1 + bv.y);
                    }
                }
            }
        }
    }
}

// ---------------------------------------------------------------------------
// Local 3x3 attention: bf16 global traffic, fp32 smem compute.
// ---------------------------------------------------------------------------
__global__ __launch_bounds__(256) void k_attn()
{
    extern __shared__ float sm[];
    float* ksh = sm;              // 18*18*36
    float* vsh = sm + 11664;
    float* qo  = sm + 2 * 11664;  // 256*36
    const int tid = threadIdx.x;
    const int b   = blockIdx.z;
    const int ti0 = blockIdx.y * 16, tj0 = blockIdx.x * 16;
    const size_t img_base = (size_t)b * (SPATIAL * SPATIAL);

    for (int head = 0; head < 4; head++) {
        if (head) __syncthreads();
        const int qoff = head * 32, koff = 128 + head * 32, voff = 256 + head * 32;
        for (int idx = tid; idx < 18 * 18 * 16; idx += 256) {
            const int c2 = (idx & 15) * 2;
            const int rc = idx >> 4;
            const int r = rc / 18, cl = rc % 18;
            const int gi = ti0 + r - 1, gj = tj0 + cl - 1;
            float k0 = 0.f, k1 = 0.f, v0 = 0.f, v1 = 0.f;
            if (gi >= 0 && gi < SPATIAL && gj >= 0 && gj < SPATIAL) {
                const __nv_bfloat16* p = g_qkv + (img_base + (size_t)gi * SPATIAL + gj) * 384;
                const __nv_bfloat162 kp = *(const __nv_bfloat162*)(p + koff + c2);
                const __nv_bfloat162 vp = *(const __nv_bfloat162*)(p + voff + c2);
                k0 = __bfloat162float(kp.x); k1 = __bfloat162float(kp.y);
                v0 = __bfloat162float(vp.x); v1 = __bfloat162float(vp.y);
            }
            ksh[rc * 36 + c2] = k0; ksh[rc * 36 + c2 + 1] = k1;
            vsh[rc * 36 + c2] = v0; vsh[rc * 36 + c2 + 1] = v1;
        }
        for (int idx = tid; idx < 256 * 16; idx += 256) {
            const int c2 = (idx & 15) * 2, t = idx >> 4;
            const int gi = ti0 + (t >> 4), gj = tj0 + (t & 15);
            const __nv_bfloat162 qp = *(const __nv_bfloat162*)(
                g_qkv + (img_base + (size_t)gi * SPATIAL + gj) * 384 + qoff + c2);
            qo[t * 36 + c2] = __bfloat162float(qp.x);
            qo[t * 36 + c2 + 1] = __bfloat162float(qp.y);
        }
        __syncthreads();

        const int t = tid, lti = t >> 4, ltj = t & 15;
        float q[32];
#pragma unroll
        for (int i = 0; i < 8; i++) {
            float4 f = *(const float4*)&qo[t * 36 + i * 4];
            q[4*i+0]=f.x; q[4*i+1]=f.y; q[4*i+2]=f.z; q[4*i+3]=f.w;
        }
        float lg[9];
#pragma unroll
        for (int nb = 0; nb < 9; nb++) {
            const float* kp = &ksh[((lti + nb/3)*18 + (ltj + nb%3))*36];
            float dd = 0.f;
#pragma unroll
            for (int i = 0; i < 8; i++) {
                float4 f = *(const float4*)&kp[i*4];
                dd += q[4*i]*f.x + q[4*i+1]*f.y + q[4*i+2]*f.z + q[4*i+3]*f.w;
            }
            lg[nb] = dd * 0.17677669529663687f;
        }
        float mx = lg[0];
#pragma unroll
        for (int nb = 1; nb < 9; nb++) mx = fmaxf(mx, lg[nb]);
        float p9[9], Z = 0.f;
#pragma unroll
        for (int nb = 0; nb < 9; nb++) { p9[nb] = expf(lg[nb] - mx); Z += p9[nb]; }
        const float inv = 1.f / Z;
        float o[32] = {};
#pragma unroll
        for (int nb = 0; nb < 9; nb++) {
            const float wgt = p9[nb] * inv;
            const float* vp = &vsh[((lti + nb/3)*18 + (ltj + nb%3))*36];
#pragma unroll
            for (int i = 0; i < 8; i++) {
                float4 f = *(const float4*)&vp[i*4];
                o[4*i+0]+=wgt*f.x; o[4*i+1]+=wgt*f.y; o[4*i+2]+=wgt*f.z; o[4*i+3]+=wgt*f.w;
            }
        }
#pragma unroll
        for (int i = 0; i < 8; i++)
            *(float4*)&qo[t*36 + i*4] = make_float4(o[4*i], o[4*i+1], o[4*i+2], o[4*i+3]);
        __syncthreads();
        for (int idx = tid; idx < 256 * 16; idx += 256) {
            const int c2 = (idx & 15) * 2, tt = idx >> 4;
            const int gi = ti0 + (tt >> 4), gj = tj0 + (tt & 15);
            *(__nv_bfloat162*)(g_o + (img_base + (size_t)gi * SPATIAL + gj) * 128
                               + head * 32 + c2) =
                __floats2bfloat162_rn(qo[tt * 36 + c2], qo[tt * 36 + c2 + 1]);
        }
    }
}

// ---------------------------------------------------------------------------
extern "C" void kernel_launch(void* const* d_in, const int* in_sizes, int n_in,
                              void* d_out, int out_size)
{
    (void)in_sizes; (void)n_in; (void)out_size;
    const float* x_in  = (const float*)d_in[0];
    const float* ln1_g = (const float*)d_in[1];
    const float* ln1_b = (const float*)d_in[2];
    const float* qkv_w = (const float*)d_in[3];
    const float* out_w = (const float*)d_in[4];
    const float* out_b = (const float*)d_in[5];
    const float* ln2_g = (const float*)d_in[6];
    const float* ln2_b = (const float*)d_in[7];
    const float* ff_w1 = (const float*)d_in[8];
    const float* ff_b1 = (const float*)d_in[9];
    const float* ff_w2 = (const float*)d_in[10];
    const float* ff_b2 = (const float*)d_in[11];
    float* X = (float*)d_out;

    const int SM_TG   = 69632;
    const int SM_ATTN = (2 * 11664 + 9216) * 4;
    cudaFuncSetAttribute(k_tg<3,1,0,0,0>, cudaFuncAttributeMaxDynamicSharedMemorySize, SM_TG);
    cudaFuncSetAttribute(k_tg<1,1,1,2,3>, cudaFuncAttributeMaxDynamicSharedMemorySize, SM_TG);
    cudaFuncSetAttribute(k_tg<4,1,0,1,4>, cudaFuncAttributeMaxDynamicSharedMemorySize, SM_TG);
    cudaFuncSetAttribute(k_tg<1,4,2,2,8>, cudaFuncAttributeMaxDynamicSharedMemorySize, SM_TG);
    cudaFuncSetAttribute(k_attn, cudaFuncAttributeMaxDynamicSharedMemorySize, SM_ATTN);

    cudaMemcpyAsync(X, x_in, (size_t)MTOT * 128 * sizeof(float),
                    cudaMemcpyDeviceToDevice, 0);
    k_prep<<<3072, 256>>>(qkv_w, out_w, ff_w1, ff_w2);

    const int GB = MTOT / 128;   // 1024 CTAs
    dim3 gAttn(8, 8, 8);
    for (int d = 0; d < 4; d++) {
        k_tg<3,1,0,0,0><<<GB, 256, SM_TG>>>(X, ln1_g + d*128, ln1_b + d*128, out_b, X, d);
        k_attn<<<gAttn, 256, SM_ATTN>>>();
        k_tg<1,1,1,2,3><<<GB, 256, SM_TG>>>(X, ln1_g, ln1_b, out_b + d*128, X, d);
        k_tg<4,1,0,1,4><<<GB, 256, SM_TG>>>(X, ln2_g + d*128, ln2_b + d*128, ff_b1 + d*512, X, d);
        k_tg<1,4,2,2,8><<<GB, 256, SM_TG>>>(X, ln2_g, ln2_b, ff_b2 + d*128, X, d);
    }
}